// round 8
// baseline (speedup 1.0000x reference)
#include <cuda_runtime.h>
#include <cuda_fp16.h>
#include <math.h>

// ---------------------------------------------------------------------------
// DeltaE2000 + MSE loss over 16.7M rgb pairs. Issue+L1tex co-bound.
// R7: all-float table init (was fp64 -> 13us/replay), HT table as half2
//     (LDS.32 instead of LDS.64), micro instruction trims.
// ---------------------------------------------------------------------------

constexpr int THREADS = 256;
constexpr int BLOCKS  = 4096;

constexpr int SRGB_N  = 2048;
constexpr int LABF_N  = 2304;                 // 18 octaves [2^-17, 2), 128/octave
constexpr unsigned LABF_BASE = 0x37000000u;   // bits of 2^-17
constexpr int HT_N    = 2048;                 // 8 octants x 256 t-bins

__device__ float   g_partials[BLOCKS];
__device__ unsigned int g_count = 0;
__device__ float   g_srgb_tab[SRGB_N];
__device__ float   g_labf_tab[LABF_N];
__device__ __half2 g_ht_tab[HT_N];

__global__ void init_tables_kernel() {
    int i = blockIdx.x * blockDim.x + threadIdx.x;
    if (i < SRGB_N) {
        float c = (i + 0.5f) / (float)SRGB_N;
        float hi = powf((c + 0.055f) / 1.055f, 2.4f);
        float lo = c / 12.92f;
        g_srgb_tab[i] = (c > 0.04045f) ? hi : lo;
    }
    if (i < LABF_N) {
        unsigned bits = LABF_BASE + ((unsigned)i << 16) + (1u << 15); // bucket center
        float t = __uint_as_float(bits);
        float f = (t > 0.008856f) ? cbrtf(t) : fmaf(7.787f, t, 16.0f / 116.0f);
        g_labf_tab[i] = f;
    }
    if (i < HT_N) {
        const float PI = 3.14159265358979323846f;
        int tbin = i & 255;
        int swp  = (i >> 8)  & 1;
        int xng  = (i >> 9)  & 1;
        int yng  = (i >> 10) & 1;
        float t = (tbin + 0.5f) / 256.0f;
        float a = atanf(t);
        float phi = swp ? (PI / 2.0f - a) : a;
        if (xng) phi = PI - phi;
        if (yng) phi = -phi;
        if (phi < 0.0f) phi += 2.0f * PI;       // havg in [0, 2pi)
        float T = 1.0f
                - 0.17f * cosf(phi - PI / 6.0f)
                + 0.24f * cosf(2.0f * phi)
                + 0.32f * cosf(3.0f * phi + PI / 30.0f)
                - 0.20f * cosf(4.0f * phi - 7.0f * PI / 20.0f);
        float hdeg = phi * (180.0f / PI);
        float u = (hdeg - 275.0f) * (1.0f / 25.0f);
        float s2t = sinf(60.0f * expf(-u * u));  // sin(2*theta)
        g_ht_tab[i] = __floats2half2_rn(T, s2t);
    }
}

__device__ __forceinline__ float warp_reduce(float v) {
#pragma unroll
    for (int o = 16; o > 0; o >>= 1) v += __shfl_down_sync(0xffffffffu, v, o);
    return v;
}

__device__ __forceinline__ float fsqrt_a(float x) {
    float r; asm("sqrt.approx.f32 %0, %1;" : "=f"(r) : "f"(x)); return r;
}
__device__ __forceinline__ float frcp_a(float x) {
    float r; asm("rcp.approx.f32 %0, %1;" : "=f"(r) : "f"(x)); return r;
}

__device__ __forceinline__ float pow7(float x) {
    float x2 = x * x;
    float x4 = x2 * x2;
    return x4 * x2 * x;
}

// sqrt(c7/(c7+P)) = rsqrt(1 + P/c7); c7=0 -> rcp=inf -> rsqrt(inf)=0 (correct)
__device__ __forceinline__ float chroma_ratio_sqrt(float c7) {
    const float POW25_7 = 6103515625.0f;
    return rsqrtf(fmaf(POW25_7, frcp_a(c7), 1.0f));
}

__device__ __forceinline__ float srgb_lookup(const float* __restrict__ tab, float c) {
    int idx = __float2int_rz(c * (float)SRGB_N);   // c in [0,1)
    return tab[idx];
}

// Branch-free: table covers [2^-17, 2); linear region baked into entries.
__device__ __forceinline__ float labf_lookup(const float* __restrict__ tab, float t) {
    int idx = (int)(__float_as_uint(t) - LABF_BASE) >> 16;
    idx = max(idx, 0);
    return tab[idx];
}

__device__ __forceinline__ void rgb2lab(const float* __restrict__ stab,
                                        const float* __restrict__ ftab,
                                        float r, float g, float b,
                                        float& L, float& A, float& Bo) {
    float lr = srgb_lookup(stab, r);
    float lg = srgb_lookup(stab, g);
    float lb = srgb_lookup(stab, b);
    float xn = (0.4124564f / 0.95047f) * lr + (0.3575761f / 0.95047f) * lg + (0.1804375f / 0.95047f) * lb;
    float yn = 0.2126729f * lr + 0.7151522f * lg + 0.072175f * lb;
    float zn = (0.0193339f / 1.08883f) * lr + (0.119192f / 1.08883f) * lg + (0.9503041f / 1.08883f) * lb;
    float fx = labf_lookup(ftab, xn);
    float fy = labf_lookup(ftab, yn);
    float fz = labf_lookup(ftab, zn);
    L  = 116.0f * fy - 16.0f;
    A  = 500.0f * (fx - fy);
    Bo = 200.0f * (fy - fz);
}

__device__ __forceinline__ float delta_e_2000(const __half2* __restrict__ httab,
                                              float L1, float a1, float b1,
                                              float L2, float a2, float b2) {
    float C1 = fsqrt_a(fmaf(a1, a1, b1 * b1));
    float C2 = fsqrt_a(fmaf(a2, a2, b2 * b2));
    float Cavg = 0.5f * (C1 + C2);
    float ratioA = chroma_ratio_sqrt(pow7(Cavg));
    float g1 = fmaf(-0.5f, ratioA, 1.5f);      // 1 + G
    float a1p = a1 * g1;
    float a2p = a2 * g1;
    float C1p = fsqrt_a(fmaf(a1p, a1p, b1 * b1));
    float C2p = fsqrt_a(fmaf(a2p, a2p, b2 * b2));

    float dL = L2 - L1;
    float dC = C2p - C1p;

    // dH = sign(sin dh) * sqrt(2*(C1p*C2p - dot))
    float dot   = fmaf(a1p, a2p, b1 * b2);
    float cross = fmaf(b2, a1p, -b1 * a2p);
    float CC    = C1p * C2p;
    float dHmag = fsqrt_a(fmaxf(2.0f * (CC - dot), 0.0f));
    float dH = copysignf(dHmag, cross);

    // Circular-mean bisector direction (angle == havg mod 2pi)
    float sx = fmaf(a1p, C2p, a2p * C1p);
    float sy = fmaf(b1,  C2p, b2  * C1p);

    // Octant-indexed lookup of {T(havg), sin(2*theta(havg))} (half2)
    float ax = fabsf(sx), ay = fabsf(sy);
    float mx = fmaxf(ax, ay), mn = fminf(ax, ay);
    float t = mn * frcp_a(mx);                 // mx==0 -> NaN -> idx 0 (harmless: dH=0)
    int idx = min(__float2int_rz(t * 256.0f), 255);
    if (ay > ax)    idx |= 256;
    if (sx < 0.0f)  idx |= 512;
    if (sy < 0.0f)  idx |= 1024;
    float2 ht = __half22float2(httab[idx]);
    float T   = ht.x;
    float rtf = ht.y;

    float Cpavg = 0.5f * (C1p + C2p);
    float RT = -2.0f * rtf * chroma_ratio_sqrt(pow7(Cpavg));

    float Lavg = 0.5f * (L1 + L2);
    float Lm = Lavg - 50.0f;
    float Lm2 = Lm * Lm;
    float SL = fmaf(0.015f * Lm2, rsqrtf(20.0f + Lm2), 1.0f);
    float SC = fmaf(0.045f, Cpavg, 1.0f);
    float SH = fmaf(0.015f, Cpavg * T, 1.0f);

    // merged divides: one rcp
    float pSCSH = SC * SH;
    float pSLSH = SL * SH;
    float pSLSC = SL * SC;
    float D = frcp_a(pSLSC * SH);
    float xx = dL * (pSCSH * D);
    float yy = dC * (pSLSH * D);
    float zz = dH * (pSLSC * D);
    return fsqrt_a(fmaf(xx, xx, fmaf(yy, yy, fmaf(zz, zz, RT * yy * zz))));
}

__device__ __forceinline__ float row_loss(const float* __restrict__ stab,
                                          const float* __restrict__ ftab,
                                          const __half2* __restrict__ httab,
                                          float pr, float pg, float pb,
                                          float tr, float tg, float tb) {
    float d0 = pr - tr, d1 = pg - tg, d2 = pb - tb;
    float sumd2 = fmaf(d0, d0, fmaf(d1, d1, d2 * d2));
    float L1, A1, B1, L2, A2, B2;
    rgb2lab(stab, ftab, pr, pg, pb, L1, A1, B1);
    rgb2lab(stab, ftab, tr, tg, tb, L2, A2, B2);
    float de = delta_e_2000(httab, L1, A1, B1, L2, A2, B2);
    return fmaf(sumd2, 0.2f / 3.0f, 0.8f * de);
}

__global__ void __launch_bounds__(THREADS, 6)
de_loss_kernel(const float* __restrict__ pred, const float* __restrict__ targ,
               float* __restrict__ out, int n, float inv_n) {
    __shared__ float   s_srgb[SRGB_N];
    __shared__ float   s_labf[LABF_N];
    __shared__ __half2 s_ht[HT_N];

    {
        const float4* gs = reinterpret_cast<const float4*>(g_srgb_tab);
        float4* ss = reinterpret_cast<float4*>(s_srgb);
        for (int i = threadIdx.x; i < SRGB_N / 4; i += THREADS) ss[i] = gs[i];
        const float4* gf = reinterpret_cast<const float4*>(g_labf_tab);
        float4* sf = reinterpret_cast<float4*>(s_labf);
        for (int i = threadIdx.x; i < LABF_N / 4; i += THREADS) sf[i] = gf[i];
        const float4* gh = reinterpret_cast<const float4*>(g_ht_tab);
        float4* shh = reinterpret_cast<float4*>(s_ht);
        for (int i = threadIdx.x; i < HT_N / 4; i += THREADS) shh[i] = gh[i];
    }
    __syncthreads();

    const int P = gridDim.x * blockDim.x;
    const int tid = blockIdx.x * blockDim.x + threadIdx.x;
    float acc = 0.0f;

    for (int base = tid * 4; base + 3 < n; base += P * 4) {
        const float4* p4 = reinterpret_cast<const float4*>(pred + (size_t)base * 3);
        const float4* t4 = reinterpret_cast<const float4*>(targ + (size_t)base * 3);
        float4 p0 = p4[0], p1 = p4[1], p2 = p4[2];
        float4 q0 = t4[0], q1 = t4[1], q2 = t4[2];

        acc += row_loss(s_srgb, s_labf, s_ht, p0.x, p0.y, p0.z,  q0.x, q0.y, q0.z);
        acc += row_loss(s_srgb, s_labf, s_ht, p0.w, p1.x, p1.y,  q0.w, q1.x, q1.y);
        acc += row_loss(s_srgb, s_labf, s_ht, p1.z, p1.w, p2.x,  q1.z, q1.w, q2.x);
        acc += row_loss(s_srgb, s_labf, s_ht, p2.y, p2.z, p2.w,  q2.y, q2.z, q2.w);
    }
    int tail_start = (n / (P * 4)) * (P * 4);
    for (int i = tail_start + tid; i < n; i += P) {
        const float* p = pred + (size_t)i * 3;
        const float* t = targ + (size_t)i * 3;
        acc += row_loss(s_srgb, s_labf, s_ht, p[0], p[1], p[2], t[0], t[1], t[2]);
    }

    float v = warp_reduce(acc);
    __shared__ float sh[THREADS / 32];
    int lane = threadIdx.x & 31;
    int wid = threadIdx.x >> 5;
    if (lane == 0) sh[wid] = v;
    __syncthreads();
    if (wid == 0) {
        v = (lane < THREADS / 32) ? sh[lane] : 0.0f;
        v = warp_reduce(v);
        if (lane == 0) g_partials[blockIdx.x] = v;
    }

    __shared__ bool is_last;
    __threadfence();
    if (threadIdx.x == 0) {
        unsigned int c = atomicAdd(&g_count, 1u);
        is_last = (c == gridDim.x - 1);
    }
    __syncthreads();
    if (is_last) {
        float a = 0.0f;
        for (int i = threadIdx.x; i < BLOCKS; i += THREADS) a += g_partials[i];
        float w = warp_reduce(a);
        if (lane == 0) sh[wid] = w;
        __syncthreads();
        if (wid == 0) {
            w = (lane < THREADS / 32) ? sh[lane] : 0.0f;
            w = warp_reduce(w);
            if (lane == 0) {
                out[0] = w * inv_n;
                g_count = 0;
            }
        }
    }
}

extern "C" void kernel_launch(void* const* d_in, const int* in_sizes, int n_in,
                              void* d_out, int out_size) {
    const float* pred = (const float*)d_in[0];
    const float* targ = (const float*)d_in[1];
    int n = in_sizes[0] / 3;
    init_tables_kernel<<<(LABF_N + 255) / 256, 256>>>();
    de_loss_kernel<<<BLOCKS, THREADS>>>(pred, targ, (float*)d_out, n, 1.0f / (float)n);
}

// round 9
// speedup vs baseline: 1.5485x; 1.5485x over previous
#include <cuda_runtime.h>
#include <cuda_fp16.h>
#include <math.h>

// ---------------------------------------------------------------------------
// DeltaE2000 + MSE loss over 16.7M rgb pairs. Issue-bound.
// R9: f32x2 packed (2 rows per instruction) dE2000 pipeline; averages folded
//     into sums (no 0.5 consts); scalar islands only at MUFU/LDS boundaries.
// ---------------------------------------------------------------------------

constexpr int THREADS = 256;
constexpr int BLOCKS  = 4096;
constexpr int SRGB_N  = 2048;
constexpr int LABF_N  = 2304;                 // 18 octaves [2^-17, 2), 128/octave
constexpr unsigned LABF_BASE = 0x37000000u;
constexpr int HT_N    = 2048;                 // 8 octants x 256 t-bins

__device__ float   g_partials[BLOCKS];
__device__ unsigned int g_count = 0;
__device__ float   g_srgb_tab[SRGB_N];
__device__ float   g_labf_tab[LABF_N];
__device__ __half2 g_ht_tab[HT_N];

__global__ void init_tables_kernel() {
    int i = blockIdx.x * blockDim.x + threadIdx.x;
    if (i < SRGB_N) {
        float c = (i + 0.5f) / (float)SRGB_N;
        float hi = powf((c + 0.055f) / 1.055f, 2.4f);
        float lo = c / 12.92f;
        g_srgb_tab[i] = (c > 0.04045f) ? hi : lo;
    }
    if (i < LABF_N) {
        unsigned bits = LABF_BASE + ((unsigned)i << 16) + (1u << 15);
        float t = __uint_as_float(bits);
        g_labf_tab[i] = (t > 0.008856f) ? cbrtf(t) : fmaf(7.787f, t, 16.0f / 116.0f);
    }
    if (i < HT_N) {
        const float PI = 3.14159265358979323846f;
        int tbin = i & 255, swp = (i >> 8) & 1, xng = (i >> 9) & 1, yng = (i >> 10) & 1;
        float t = (tbin + 0.5f) / 256.0f;
        float a = atanf(t);
        float phi = swp ? (PI / 2.0f - a) : a;
        if (xng) phi = PI - phi;
        if (yng) phi = -phi;
        if (phi < 0.0f) phi += 2.0f * PI;
        float T = 1.0f - 0.17f * cosf(phi - PI / 6.0f) + 0.24f * cosf(2.0f * phi)
                + 0.32f * cosf(3.0f * phi + PI / 30.0f)
                - 0.20f * cosf(4.0f * phi - 7.0f * PI / 20.0f);
        float hdeg = phi * (180.0f / PI);
        float u = (hdeg - 275.0f) * (1.0f / 25.0f);
        g_ht_tab[i] = __floats2half2_rn(T, sinf(60.0f * expf(-u * u)));
    }
}

// ---------------- scalar helpers ----------------
__device__ __forceinline__ float warp_reduce(float v) {
#pragma unroll
    for (int o = 16; o > 0; o >>= 1) v += __shfl_down_sync(0xffffffffu, v, o);
    return v;
}
__device__ __forceinline__ float fsqrt_a(float x) {
    float r; asm("sqrt.approx.f32 %0, %1;" : "=f"(r) : "f"(x)); return r;
}
__device__ __forceinline__ float frcp_a(float x) {
    float r; asm("rcp.approx.f32 %0, %1;" : "=f"(r) : "f"(x)); return r;
}

// ---------------- f32x2 packed helpers ----------------
typedef unsigned long long u64;
__device__ __forceinline__ u64 pk2(float lo, float hi) {
    u64 r; asm("mov.b64 %0, {%1, %2};" : "=l"(r) : "f"(lo), "f"(hi)); return r;
}
__device__ __forceinline__ void up2(u64 v, float& lo, float& hi) {
    asm("mov.b64 {%0, %1}, %2;" : "=f"(lo), "=f"(hi) : "l"(v));
}
__device__ __forceinline__ u64 f2mul(u64 a, u64 b) {
    u64 r; asm("mul.rn.f32x2 %0, %1, %2;" : "=l"(r) : "l"(a), "l"(b)); return r;
}
__device__ __forceinline__ u64 f2add(u64 a, u64 b) {
    u64 r; asm("add.rn.f32x2 %0, %1, %2;" : "=l"(r) : "l"(a), "l"(b)); return r;
}
__device__ __forceinline__ u64 f2fma(u64 a, u64 b, u64 c) {
    u64 r; asm("fma.rn.f32x2 %0, %1, %2, %3;" : "=l"(r) : "l"(a), "l"(b), "l"(c)); return r;
}
__device__ __forceinline__ u64 f2neg(u64 a) { return a ^ 0x8000000080000000ull; }

// ---------------- table lookups ----------------
__device__ __forceinline__ float srgb_lookup(const float* __restrict__ tab, float c) {
    int idx = __float2int_rz(c * (float)SRGB_N);
    return tab[idx];
}
__device__ __forceinline__ float labf_lookup(const float* __restrict__ tab, float t) {
    int idx = (int)(__float_as_uint(t) - LABF_BASE) >> 16;
    idx = max(idx, 0);
    return tab[idx];
}
__device__ __forceinline__ void rgb2lab(const float* __restrict__ stab,
                                        const float* __restrict__ ftab,
                                        float r, float g, float b,
                                        float& L, float& A, float& Bo) {
    float lr = srgb_lookup(stab, r);
    float lg = srgb_lookup(stab, g);
    float lb = srgb_lookup(stab, b);
    float xn = (0.4124564f / 0.95047f) * lr + (0.3575761f / 0.95047f) * lg + (0.1804375f / 0.95047f) * lb;
    float yn = 0.2126729f * lr + 0.7151522f * lg + 0.072175f * lb;
    float zn = (0.0193339f / 1.08883f) * lr + (0.119192f / 1.08883f) * lg + (0.9503041f / 1.08883f) * lb;
    float fx = labf_lookup(ftab, xn);
    float fy = labf_lookup(ftab, yn);
    float fz = labf_lookup(ftab, zn);
    L  = 116.0f * fy - 16.0f;
    A  = 500.0f * (fx - fy);
    Bo = 200.0f * (fy - fz);
}
__device__ __forceinline__ void hue_lookup(const __half2* __restrict__ httab,
                                           float sx, float sy, float& T, float& rtf) {
    float ax = fabsf(sx), ay = fabsf(sy);
    float mx = fmaxf(ax, ay), mn = fminf(ax, ay);
    float t = mn * frcp_a(mx);               // mx==0 -> NaN -> idx clamps; dH=0 there
    int idx = min(__float2int_rz(t * 256.0f), 255);
    idx = max(idx, 0);
    if (ay > ax)    idx |= 256;
    if (sx < 0.0f)  idx |= 512;
    if (sy < 0.0f)  idx |= 1024;
    float2 ht = __half22float2(httab[idx]);
    T = ht.x; rtf = ht.y;
}

// ratio = sqrt(S^7/(S^7+128*25^7)) for S = C1+C2  (averages folded)
__device__ __forceinline__ void ratio2(u64 pS, float& ru, float& rv) {
    u64 s2 = f2mul(pS, pS);
    u64 s4 = f2mul(s2, s2);
    u64 s7 = f2mul(f2mul(s4, s2), pS);
    float au, av; up2(s7, au, av);
    const float P = 6103515625.0f * 128.0f;
    ru = rsqrtf(fmaf(P, frcp_a(au), 1.0f));
    rv = rsqrtf(fmaf(P, frcp_a(av), 1.0f));
}

// ---------------- packed pair deltaE (rows u, v) ----------------
__device__ __forceinline__ void pair_de(const __half2* __restrict__ httab,
    u64 pONE, u64 p00225, u64 p00075, u64 p80, u64 pN100,
    float L1u, float a1u, float b1u, float L2u, float a2u, float b2u,
    float L1v, float a1v, float b1v, float L2v, float a2v, float b2v,
    float& deu, float& dev)
{
    u64 pA1 = pk2(a1u, a1v), pB1 = pk2(b1u, b1v);
    u64 pA2 = pk2(a2u, a2v), pB2 = pk2(b2u, b2v);
    u64 pB1sq = f2mul(pB1, pB1), pB2sq = f2mul(pB2, pB2);
    u64 pC1sq = f2fma(pA1, pA1, pB1sq), pC2sq = f2fma(pA2, pA2, pB2sq);
    float w0, w1, w2, w3;
    up2(pC1sq, w0, w1); up2(pC2sq, w2, w3);
    u64 pC1 = pk2(fsqrt_a(w0), fsqrt_a(w1));
    u64 pC2 = pk2(fsqrt_a(w2), fsqrt_a(w3));

    float ru, rv;
    ratio2(f2add(pC1, pC2), ru, rv);
    u64 pG = pk2(fmaf(-0.5f, ru, 1.5f), fmaf(-0.5f, rv, 1.5f));   // 1+G
    u64 pA1p = f2mul(pA1, pG), pA2p = f2mul(pA2, pG);
    u64 pC1psq = f2fma(pA1p, pA1p, pB1sq), pC2psq = f2fma(pA2p, pA2p, pB2sq);
    up2(pC1psq, w0, w1); up2(pC2psq, w2, w3);
    u64 pC1p = pk2(fsqrt_a(w0), fsqrt_a(w1));
    u64 pC2p = pk2(fsqrt_a(w2), fsqrt_a(w3));

    // dH = sign(cross) * sqrt(2*(C1p*C2p - dot))
    u64 pdot = f2fma(pA1p, pA2p, f2mul(pB1, pB2));
    u64 pcr  = f2fma(pB2, pA1p, f2neg(f2mul(pB1, pA2p)));
    u64 parg = f2add(f2mul(pC1p, pC2p), f2neg(pdot));
    parg = f2add(parg, parg);
    float agu, agv, cru, crv;
    up2(parg, agu, agv); up2(pcr, cru, crv);
    float dHu = copysignf(fsqrt_a(fmaxf(agu, 0.0f)), cru);
    float dHv = copysignf(fsqrt_a(fmaxf(agv, 0.0f)), crv);

    // hue bisector (sx, sy) per row
    u64 psx = f2fma(pA1p, pC2p, f2mul(pA2p, pC1p));
    u64 psy = f2fma(pB1,  pC2p, f2mul(pB2,  pC1p));
    float sxu, sxv, syu, syv;
    up2(psx, sxu, sxv); up2(psy, syu, syv);
    float Tu, rtfu, Tv, rtfv;
    hue_lookup(httab, sxu, syu, Tu, rtfu);
    hue_lookup(httab, sxv, syv, Tv, rtfv);

    // S' = C1p + C2p; RC via folded ratio; RT = -2*rtf*rc
    u64 pSp = f2add(pC1p, pC2p);
    float rcu, rcv;
    ratio2(pSp, rcu, rcv);
    u64 pRT = pk2(-2.0f * rtfu * rcu, -2.0f * rtfv * rcv);

    // SL = 1 + 0.0075*Lm'^2*rsqrt(80+Lm'^2), Lm' = L1+L2-100
    u64 pL1 = pk2(L1u, L1v), pL2 = pk2(L2u, L2v);
    u64 pLm = f2add(f2add(pL1, pL2), pN100);
    u64 pLm2 = f2mul(pLm, pLm);
    float ldu, ldv;
    up2(f2add(pLm2, p80), ldu, ldv);
    u64 pRS = pk2(rsqrtf(ldu), rsqrtf(ldv));
    u64 pSL = f2fma(f2mul(pLm2, p00075), pRS, pONE);
    u64 pSC = f2fma(p00225, pSp, pONE);
    u64 pSH = f2fma(f2mul(pSp, pk2(Tu, Tv)), p00075, pONE);

    // merged divides: one rcp per row
    u64 pSCSH = f2mul(pSC, pSH), pSLSH = f2mul(pSL, pSH), pSLSC = f2mul(pSL, pSC);
    float dnu, dnv;
    up2(f2mul(pSLSC, pSH), dnu, dnv);
    u64 pD = pk2(frcp_a(dnu), frcp_a(dnv));
    u64 xx = f2mul(f2add(pL2, f2neg(pL1)),  f2mul(pSCSH, pD));
    u64 yy = f2mul(f2add(pC2p, f2neg(pC1p)), f2mul(pSLSH, pD));
    u64 zz = f2mul(pk2(dHu, dHv),            f2mul(pSLSC, pD));
    u64 sum = f2fma(xx, xx, f2fma(yy, yy, f2fma(zz, zz, f2mul(pRT, f2mul(yy, zz)))));
    float su, sv;
    up2(sum, su, sv);
    deu = fsqrt_a(su);
    dev = fsqrt_a(sv);
}

__device__ __forceinline__ float pair_loss(const float* __restrict__ stab,
    const float* __restrict__ ftab, const __half2* __restrict__ httab,
    u64 pONE, u64 p00225, u64 p00075, u64 p80, u64 pN100,
    float pru, float pgu, float pbu, float tru, float tgu, float tbu,
    float prv, float pgv, float pbv, float trv, float tgv, float tbv)
{
    float d0 = pru - tru, d1 = pgu - tgu, d2 = pbu - tbu;
    float m_u = fmaf(d0, d0, fmaf(d1, d1, d2 * d2));
    d0 = prv - trv; d1 = pgv - tgv; d2 = pbv - tbv;
    float m_v = fmaf(d0, d0, fmaf(d1, d1, d2 * d2));

    float L1u, A1u, B1u, L2u, A2u, B2u, L1v, A1v, B1v, L2v, A2v, B2v;
    rgb2lab(stab, ftab, pru, pgu, pbu, L1u, A1u, B1u);
    rgb2lab(stab, ftab, tru, tgu, tbu, L2u, A2u, B2u);
    rgb2lab(stab, ftab, prv, pgv, pbv, L1v, A1v, B1v);
    rgb2lab(stab, ftab, trv, tgv, tbv, L2v, A2v, B2v);

    float deu, dev;
    pair_de(httab, pONE, p00225, p00075, p80, pN100,
            L1u, A1u, B1u, L2u, A2u, B2u,
            L1v, A1v, B1v, L2v, A2v, B2v, deu, dev);
    return fmaf(m_u + m_v, 0.2f / 3.0f, 0.8f * (deu + dev));
}

__global__ void __launch_bounds__(THREADS, 4)
de_loss_kernel(const float* __restrict__ pred, const float* __restrict__ targ,
               float* __restrict__ out, int n, float inv_n) {
    __shared__ float   s_srgb[SRGB_N];
    __shared__ float   s_labf[LABF_N];
    __shared__ __half2 s_ht[HT_N];
    {
        const float4* gs = reinterpret_cast<const float4*>(g_srgb_tab);
        float4* ss = reinterpret_cast<float4*>(s_srgb);
        for (int i = threadIdx.x; i < SRGB_N / 4; i += THREADS) ss[i] = gs[i];
        const float4* gf = reinterpret_cast<const float4*>(g_labf_tab);
        float4* sf = reinterpret_cast<float4*>(s_labf);
        for (int i = threadIdx.x; i < LABF_N / 4; i += THREADS) sf[i] = gf[i];
        const float4* gh = reinterpret_cast<const float4*>(g_ht_tab);
        float4* shh = reinterpret_cast<float4*>(s_ht);
        for (int i = threadIdx.x; i < HT_N / 4; i += THREADS) shh[i] = gh[i];
    }
    __syncthreads();

    const u64 pONE   = pk2(1.0f, 1.0f);
    const u64 p00225 = pk2(0.0225f, 0.0225f);
    const u64 p00075 = pk2(0.0075f, 0.0075f);
    const u64 p80    = pk2(80.0f, 80.0f);
    const u64 pN100  = pk2(-100.0f, -100.0f);

    const int P = gridDim.x * blockDim.x;
    const int tid = blockIdx.x * blockDim.x + threadIdx.x;
    float acc = 0.0f;

    for (int base = tid * 4; base + 3 < n; base += P * 4) {
        const float4* p4 = reinterpret_cast<const float4*>(pred + (size_t)base * 3);
        const float4* t4 = reinterpret_cast<const float4*>(targ + (size_t)base * 3);
        float4 p0 = p4[0], p1 = p4[1], p2 = p4[2];
        float4 q0 = t4[0], q1 = t4[1], q2 = t4[2];

        acc += pair_loss(s_srgb, s_labf, s_ht, pONE, p00225, p00075, p80, pN100,
                         p0.x, p0.y, p0.z,  q0.x, q0.y, q0.z,
                         p0.w, p1.x, p1.y,  q0.w, q1.x, q1.y);
        acc += pair_loss(s_srgb, s_labf, s_ht, pONE, p00225, p00075, p80, pN100,
                         p1.z, p1.w, p2.x,  q1.z, q1.w, q2.x,
                         p2.y, p2.z, p2.w,  q2.y, q2.z, q2.w);
    }
    int tail_start = (n / (P * 4)) * (P * 4);
    for (int i = tail_start + tid; i < n; i += P) {
        const float* p = pred + (size_t)i * 3;
        const float* t = targ + (size_t)i * 3;
        // tail handled as a degenerate pair (row duplicated, halved)
        float l2 = pair_loss(s_srgb, s_labf, s_ht, pONE, p00225, p00075, p80, pN100,
                             p[0], p[1], p[2], t[0], t[1], t[2],
                             p[0], p[1], p[2], t[0], t[1], t[2]);
        acc += 0.5f * l2;
    }

    float v = warp_reduce(acc);
    __shared__ float sh[THREADS / 32];
    int lane = threadIdx.x & 31;
    int wid = threadIdx.x >> 5;
    if (lane == 0) sh[wid] = v;
    __syncthreads();
    if (wid == 0) {
        v = (lane < THREADS / 32) ? sh[lane] : 0.0f;
        v = warp_reduce(v);
        if (lane == 0) g_partials[blockIdx.x] = v;
    }

    __shared__ bool is_last;
    __threadfence();
    if (threadIdx.x == 0) {
        unsigned int c = atomicAdd(&g_count, 1u);
        is_last = (c == gridDim.x - 1);
    }
    __syncthreads();
    if (is_last) {
        float a = 0.0f;
        for (int i = threadIdx.x; i < BLOCKS; i += THREADS) a += g_partials[i];
        float w = warp_reduce(a);
        if (lane == 0) sh[wid] = w;
        __syncthreads();
        if (wid == 0) {
            w = (lane < THREADS / 32) ? sh[lane] : 0.0f;
            w = warp_reduce(w);
            if (lane == 0) {
                out[0] = w * inv_n;
                g_count = 0;
            }
        }
    }
}

extern "C" void kernel_launch(void* const* d_in, const int* in_sizes, int n_in,
                              void* d_out, int out_size) {
    const float* pred = (const float*)d_in[0];
    const float* targ = (const float*)d_in[1];
    int n = in_sizes[0] / 3;
    init_tables_kernel<<<(LABF_N + 255) / 256, 256>>>();
    de_loss_kernel<<<BLOCKS, THREADS>>>(pred, targ, (float*)d_out, n, 1.0f / (float)n);
}

// round 10
// speedup vs baseline: 1.6304x; 1.0529x over previous
#include <cuda_runtime.h>
#include <cuda_fp16.h>
#include <math.h>

// ---------------------------------------------------------------------------
// DeltaE2000 + MSE loss over 16.7M rgb pairs.
// R10: keep f32x2 packed pipeline (R9) but recover occupancy (5 blocks/SM),
//      and replace all F2I index conversions with float-mantissa bit tricks
//      (sRGB table and a u=|sy|/(|sx|+|sy|)-parameterized hue table).
// ---------------------------------------------------------------------------

constexpr int THREADS = 256;
constexpr int BLOCKS  = 4096;
constexpr int SRGB_N  = 2048;
constexpr int LABF_N  = 2304;                 // 18 octaves [2^-17, 2), 128/octave
constexpr unsigned LABF_BASE = 0x37000000u;
constexpr int HT_N    = 4096;                 // 4 quadrants x 1024 u-bins

__device__ float   g_partials[BLOCKS];
__device__ unsigned int g_count = 0;
__device__ float   g_srgb_tab[SRGB_N];
__device__ float   g_labf_tab[LABF_N];
__device__ __half2 g_ht_tab[HT_N];

__global__ void init_tables_kernel() {
    int i = blockIdx.x * blockDim.x + threadIdx.x;
    if (i < SRGB_N) {
        float c = (i + 0.5f) / (float)SRGB_N;
        float hi = powf((c + 0.055f) / 1.055f, 2.4f);
        float lo = c / 12.92f;
        g_srgb_tab[i] = (c > 0.04045f) ? hi : lo;
    }
    if (i < LABF_N) {
        unsigned bits = LABF_BASE + ((unsigned)i << 16) + (1u << 15);
        float t = __uint_as_float(bits);
        g_labf_tab[i] = (t > 0.008856f) ? cbrtf(t) : fmaf(7.787f, t, 16.0f / 116.0f);
    }
    if (i < HT_N) {
        const float PI = 3.14159265358979323846f;
        int ubin = i & 1023, xng = (i >> 10) & 1, yng = (i >> 11) & 1;
        float u = (ubin + 0.5f) / 1024.0f;      // |sy| / (|sx|+|sy|)
        float phi = atan2f(u, 1.0f - u);        // [0, pi/2]
        if (xng) phi = PI - phi;
        if (yng) phi = -phi;
        if (phi < 0.0f) phi += 2.0f * PI;       // havg in [0, 2pi)
        float T = 1.0f - 0.17f * cosf(phi - PI / 6.0f) + 0.24f * cosf(2.0f * phi)
                + 0.32f * cosf(3.0f * phi + PI / 30.0f)
                - 0.20f * cosf(4.0f * phi - 7.0f * PI / 20.0f);
        float hdeg = phi * (180.0f / PI);
        float w = (hdeg - 275.0f) * (1.0f / 25.0f);
        g_ht_tab[i] = __floats2half2_rn(T, sinf(60.0f * expf(-w * w)));
    }
}

// ---------------- scalar helpers ----------------
__device__ __forceinline__ float warp_reduce(float v) {
#pragma unroll
    for (int o = 16; o > 0; o >>= 1) v += __shfl_down_sync(0xffffffffu, v, o);
    return v;
}
__device__ __forceinline__ float fsqrt_a(float x) {
    float r; asm("sqrt.approx.f32 %0, %1;" : "=f"(r) : "f"(x)); return r;
}
__device__ __forceinline__ float frcp_a(float x) {
    float r; asm("rcp.approx.f32 %0, %1;" : "=f"(r) : "f"(x)); return r;
}

// ---------------- f32x2 packed helpers ----------------
typedef unsigned long long u64;
__device__ __forceinline__ u64 pk2(float lo, float hi) {
    u64 r; asm("mov.b64 %0, {%1, %2};" : "=l"(r) : "f"(lo), "f"(hi)); return r;
}
__device__ __forceinline__ void up2(u64 v, float& lo, float& hi) {
    asm("mov.b64 {%0, %1}, %2;" : "=f"(lo), "=f"(hi) : "l"(v));
}
__device__ __forceinline__ u64 f2mul(u64 a, u64 b) {
    u64 r; asm("mul.rn.f32x2 %0, %1, %2;" : "=l"(r) : "l"(a), "l"(b)); return r;
}
__device__ __forceinline__ u64 f2add(u64 a, u64 b) {
    u64 r; asm("add.rn.f32x2 %0, %1, %2;" : "=l"(r) : "l"(a), "l"(b)); return r;
}
__device__ __forceinline__ u64 f2fma(u64 a, u64 b, u64 c) {
    u64 r; asm("fma.rn.f32x2 %0, %1, %2, %3;" : "=l"(r) : "l"(a), "l"(b), "l"(c)); return r;
}
__device__ __forceinline__ u64 f2neg(u64 a) { return a ^ 0x8000000080000000ull; }

// ---------------- table lookups (bit-trick indices, no F2I) ----------------
__device__ __forceinline__ float srgb_lookup(const float* __restrict__ tab, float c) {
    // c in [0,1): mantissa of (1+c) top 11 bits == floor(c*2048)
    unsigned bits = __float_as_uint(c + 1.0f);
    return tab[(bits >> 12) & 2047u];
}
__device__ __forceinline__ float labf_lookup(const float* __restrict__ tab, float t) {
    int idx = (int)(__float_as_uint(t) - LABF_BASE) >> 16;
    idx = max(idx, 0);
    return tab[idx];
}
__device__ __forceinline__ void rgb2lab(const float* __restrict__ stab,
                                        const float* __restrict__ ftab,
                                        float r, float g, float b,
                                        float& L, float& A, float& Bo) {
    float lr = srgb_lookup(stab, r);
    float lg = srgb_lookup(stab, g);
    float lb = srgb_lookup(stab, b);
    float xn = (0.4124564f / 0.95047f) * lr + (0.3575761f / 0.95047f) * lg + (0.1804375f / 0.95047f) * lb;
    float yn = 0.2126729f * lr + 0.7151522f * lg + 0.072175f * lb;
    float zn = (0.0193339f / 1.08883f) * lr + (0.119192f / 1.08883f) * lg + (0.9503041f / 1.08883f) * lb;
    float fx = labf_lookup(ftab, xn);
    float fy = labf_lookup(ftab, yn);
    float fz = labf_lookup(ftab, zn);
    L  = 116.0f * fy - 16.0f;
    A  = 500.0f * (fx - fy);
    Bo = 200.0f * (fy - fz);
}
__device__ __forceinline__ void hue_lookup(const __half2* __restrict__ httab,
                                           float sx, float sy, float& T, float& rtf) {
    float ax = fabsf(sx), ay = fabsf(sy);
    float u = ay * frcp_a(ax + ay);            // [0,1]; degenerate -> harmless bin
    unsigned bits = __float_as_uint(u + 1.0f);
    int idx = (int)((bits >> 13) & 1023u);
    if (sx < 0.0f) idx |= 1024;
    if (sy < 0.0f) idx |= 2048;
    float2 ht = __half22float2(httab[idx]);
    T = ht.x; rtf = ht.y;
}

// ratio = sqrt(S^7/(S^7+128*25^7)) for S = C1+C2  (averages folded)
__device__ __forceinline__ void ratio2(u64 pS, float& ru, float& rv) {
    u64 s2 = f2mul(pS, pS);
    u64 s4 = f2mul(s2, s2);
    u64 s7 = f2mul(f2mul(s4, s2), pS);
    float au, av; up2(s7, au, av);
    const float P = 6103515625.0f * 128.0f;
    ru = rsqrtf(fmaf(P, frcp_a(au), 1.0f));
    rv = rsqrtf(fmaf(P, frcp_a(av), 1.0f));
}

// ---------------- packed pair deltaE (rows u, v) ----------------
__device__ __forceinline__ void pair_de(const __half2* __restrict__ httab,
    u64 pONE, u64 p00225, u64 p00075, u64 p80, u64 pN100,
    float L1u, float a1u, float b1u, float L2u, float a2u, float b2u,
    float L1v, float a1v, float b1v, float L2v, float a2v, float b2v,
    float& deu, float& dev)
{
    u64 pA1 = pk2(a1u, a1v), pB1 = pk2(b1u, b1v);
    u64 pA2 = pk2(a2u, a2v), pB2 = pk2(b2u, b2v);
    u64 pB1sq = f2mul(pB1, pB1), pB2sq = f2mul(pB2, pB2);
    u64 pC1sq = f2fma(pA1, pA1, pB1sq), pC2sq = f2fma(pA2, pA2, pB2sq);
    float w0, w1, w2, w3;
    up2(pC1sq, w0, w1); up2(pC2sq, w2, w3);
    u64 pC1 = pk2(fsqrt_a(w0), fsqrt_a(w1));
    u64 pC2 = pk2(fsqrt_a(w2), fsqrt_a(w3));

    float ru, rv;
    ratio2(f2add(pC1, pC2), ru, rv);
    u64 pG = pk2(fmaf(-0.5f, ru, 1.5f), fmaf(-0.5f, rv, 1.5f));   // 1+G
    u64 pA1p = f2mul(pA1, pG), pA2p = f2mul(pA2, pG);
    u64 pC1psq = f2fma(pA1p, pA1p, pB1sq), pC2psq = f2fma(pA2p, pA2p, pB2sq);
    up2(pC1psq, w0, w1); up2(pC2psq, w2, w3);
    u64 pC1p = pk2(fsqrt_a(w0), fsqrt_a(w1));
    u64 pC2p = pk2(fsqrt_a(w2), fsqrt_a(w3));

    // dH = sign(cross) * sqrt(2*(C1p*C2p - dot))
    u64 pdot = f2fma(pA1p, pA2p, f2mul(pB1, pB2));
    u64 pcr  = f2fma(pB2, pA1p, f2neg(f2mul(pB1, pA2p)));
    u64 parg = f2add(f2mul(pC1p, pC2p), f2neg(pdot));
    parg = f2add(parg, parg);
    float agu, agv, cru, crv;
    up2(parg, agu, agv); up2(pcr, cru, crv);
    float dHu = copysignf(fsqrt_a(fmaxf(agu, 0.0f)), cru);
    float dHv = copysignf(fsqrt_a(fmaxf(agv, 0.0f)), crv);

    // hue bisector (sx, sy) per row
    u64 psx = f2fma(pA1p, pC2p, f2mul(pA2p, pC1p));
    u64 psy = f2fma(pB1,  pC2p, f2mul(pB2,  pC1p));
    float sxu, sxv, syu, syv;
    up2(psx, sxu, sxv); up2(psy, syu, syv);
    float Tu, rtfu, Tv, rtfv;
    hue_lookup(httab, sxu, syu, Tu, rtfu);
    hue_lookup(httab, sxv, syv, Tv, rtfv);

    // S' = C1p + C2p; RC via folded ratio; RT = -2*rtf*rc
    u64 pSp = f2add(pC1p, pC2p);
    float rcu, rcv;
    ratio2(pSp, rcu, rcv);
    u64 pRT = pk2(-2.0f * rtfu * rcu, -2.0f * rtfv * rcv);

    // SL = 1 + 0.0075*Lm'^2*rsqrt(80+Lm'^2), Lm' = L1+L2-100
    u64 pL1 = pk2(L1u, L1v), pL2 = pk2(L2u, L2v);
    u64 pLm = f2add(f2add(pL1, pL2), pN100);
    u64 pLm2 = f2mul(pLm, pLm);
    float ldu, ldv;
    up2(f2add(pLm2, p80), ldu, ldv);
    u64 pRS = pk2(rsqrtf(ldu), rsqrtf(ldv));
    u64 pSL = f2fma(f2mul(pLm2, p00075), pRS, pONE);
    u64 pSC = f2fma(p00225, pSp, pONE);
    u64 pSH = f2fma(f2mul(pSp, pk2(Tu, Tv)), p00075, pONE);

    // merged divides: one rcp per row
    u64 pSCSH = f2mul(pSC, pSH), pSLSH = f2mul(pSL, pSH), pSLSC = f2mul(pSL, pSC);
    float dnu, dnv;
    up2(f2mul(pSLSC, pSH), dnu, dnv);
    u64 pD = pk2(frcp_a(dnu), frcp_a(dnv));
    u64 xx = f2mul(f2add(pL2, f2neg(pL1)),   f2mul(pSCSH, pD));
    u64 yy = f2mul(f2add(pC2p, f2neg(pC1p)), f2mul(pSLSH, pD));
    u64 zz = f2mul(pk2(dHu, dHv),            f2mul(pSLSC, pD));
    u64 sum = f2fma(xx, xx, f2fma(yy, yy, f2fma(zz, zz, f2mul(pRT, f2mul(yy, zz)))));
    float su, sv;
    up2(sum, su, sv);
    deu = fsqrt_a(su);
    dev = fsqrt_a(sv);
}

__device__ __forceinline__ float pair_loss(const float* __restrict__ stab,
    const float* __restrict__ ftab, const __half2* __restrict__ httab,
    u64 pONE, u64 p00225, u64 p00075, u64 p80, u64 pN100,
    float pru, float pgu, float pbu, float tru, float tgu, float tbu,
    float prv, float pgv, float pbv, float trv, float tgv, float tbv)
{
    float d0 = pru - tru, d1 = pgu - tgu, d2 = pbu - tbu;
    float m_u = fmaf(d0, d0, fmaf(d1, d1, d2 * d2));
    d0 = prv - trv; d1 = pgv - tgv; d2 = pbv - tbv;
    float m_v = fmaf(d0, d0, fmaf(d1, d1, d2 * d2));

    float L1u, A1u, B1u, L2u, A2u, B2u, L1v, A1v, B1v, L2v, A2v, B2v;
    rgb2lab(stab, ftab, pru, pgu, pbu, L1u, A1u, B1u);
    rgb2lab(stab, ftab, tru, tgu, tbu, L2u, A2u, B2u);
    rgb2lab(stab, ftab, prv, pgv, pbv, L1v, A1v, B1v);
    rgb2lab(stab, ftab, trv, tgv, tbv, L2v, A2v, B2v);

    float deu, dev;
    pair_de(httab, pONE, p00225, p00075, p80, pN100,
            L1u, A1u, B1u, L2u, A2u, B2u,
            L1v, A1v, B1v, L2v, A2v, B2v, deu, dev);
    return fmaf(m_u + m_v, 0.2f / 3.0f, 0.8f * (deu + dev));
}

__global__ void __launch_bounds__(THREADS, 5)
de_loss_kernel(const float* __restrict__ pred, const float* __restrict__ targ,
               float* __restrict__ out, int n, float inv_n) {
    __shared__ float   s_srgb[SRGB_N];
    __shared__ float   s_labf[LABF_N];
    __shared__ __half2 s_ht[HT_N];
    {
        const float4* gs = reinterpret_cast<const float4*>(g_srgb_tab);
        float4* ss = reinterpret_cast<float4*>(s_srgb);
        for (int i = threadIdx.x; i < SRGB_N / 4; i += THREADS) ss[i] = gs[i];
        const float4* gf = reinterpret_cast<const float4*>(g_labf_tab);
        float4* sf = reinterpret_cast<float4*>(s_labf);
        for (int i = threadIdx.x; i < LABF_N / 4; i += THREADS) sf[i] = gf[i];
        const float4* gh = reinterpret_cast<const float4*>(g_ht_tab);
        float4* shh = reinterpret_cast<float4*>(s_ht);
        for (int i = threadIdx.x; i < HT_N / 4; i += THREADS) shh[i] = gh[i];
    }
    __syncthreads();

    const u64 pONE   = pk2(1.0f, 1.0f);
    const u64 p00225 = pk2(0.0225f, 0.0225f);
    const u64 p00075 = pk2(0.0075f, 0.0075f);
    const u64 p80    = pk2(80.0f, 80.0f);
    const u64 pN100  = pk2(-100.0f, -100.0f);

    const int P = gridDim.x * blockDim.x;
    const int tid = blockIdx.x * blockDim.x + threadIdx.x;
    float acc = 0.0f;

    for (int base = tid * 4; base + 3 < n; base += P * 4) {
        const float4* p4 = reinterpret_cast<const float4*>(pred + (size_t)base * 3);
        const float4* t4 = reinterpret_cast<const float4*>(targ + (size_t)base * 3);
        float4 p0 = p4[0], p1 = p4[1], p2 = p4[2];
        float4 q0 = t4[0], q1 = t4[1], q2 = t4[2];

        acc += pair_loss(s_srgb, s_labf, s_ht, pONE, p00225, p00075, p80, pN100,
                         p0.x, p0.y, p0.z,  q0.x, q0.y, q0.z,
                         p0.w, p1.x, p1.y,  q0.w, q1.x, q1.y);
        acc += pair_loss(s_srgb, s_labf, s_ht, pONE, p00225, p00075, p80, pN100,
                         p1.z, p1.w, p2.x,  q1.z, q1.w, q2.x,
                         p2.y, p2.z, p2.w,  q2.y, q2.z, q2.w);
    }
    int tail_start = (n / (P * 4)) * (P * 4);
    for (int i = tail_start + tid; i < n; i += P) {
        const float* p = pred + (size_t)i * 3;
        const float* t = targ + (size_t)i * 3;
        float l2 = pair_loss(s_srgb, s_labf, s_ht, pONE, p00225, p00075, p80, pN100,
                             p[0], p[1], p[2], t[0], t[1], t[2],
                             p[0], p[1], p[2], t[0], t[1], t[2]);
        acc += 0.5f * l2;
    }

    float v = warp_reduce(acc);
    __shared__ float sh[THREADS / 32];
    int lane = threadIdx.x & 31;
    int wid = threadIdx.x >> 5;
    if (lane == 0) sh[wid] = v;
    __syncthreads();
    if (wid == 0) {
        v = (lane < THREADS / 32) ? sh[lane] : 0.0f;
        v = warp_reduce(v);
        if (lane == 0) g_partials[blockIdx.x] = v;
    }

    __shared__ bool is_last;
    __threadfence();
    if (threadIdx.x == 0) {
        unsigned int c = atomicAdd(&g_count, 1u);
        is_last = (c == gridDim.x - 1);
    }
    __syncthreads();
    if (is_last) {
        float a = 0.0f;
        for (int i = threadIdx.x; i < BLOCKS; i += THREADS) a += g_partials[i];
        float w = warp_reduce(a);
        if (lane == 0) sh[wid] = w;
        __syncthreads();
        if (wid == 0) {
            w = (lane < THREADS / 32) ? sh[lane] : 0.0f;
            w = warp_reduce(w);
            if (lane == 0) {
                out[0] = w * inv_n;
                g_count = 0;
            }
        }
    }
}

extern "C" void kernel_launch(void* const* d_in, const int* in_sizes, int n_in,
                              void* d_out, int out_size) {
    const float* pred = (const float*)d_in[0];
    const float* targ = (const float*)d_in[1];
    int n = in_sizes[0] / 3;
    init_tables_kernel<<<(HT_N + 255) / 256, 256>>>();
    de_loss_kernel<<<BLOCKS, THREADS>>>(pred, targ, (float*)d_out, n, 1.0f / (float)n);
}

// round 11
// speedup vs baseline: 1.6619x; 1.0193x over previous
#include <cuda_runtime.h>
#include <cuda_fp16.h>
#include <math.h>

// ---------------------------------------------------------------------------
// DeltaE2000 + MSE loss over 16.7M rgb pairs. Issue + LDS-crossbar co-bound.
// R11: ratio via x*rsqrt(x*(x+P)) (-2 MUFU/row), integer sign-merge in hue
//      index (no predicates), dual accumulators for cross-pair ILP.
// ---------------------------------------------------------------------------

constexpr int THREADS = 256;
constexpr int BLOCKS  = 4096;
constexpr int SRGB_N  = 2048;
constexpr int LABF_N  = 2304;                 // 18 octaves [2^-17, 2), 128/octave
constexpr unsigned LABF_BASE = 0x37000000u;
constexpr int HT_N    = 4096;                 // 4 quadrants x 1024 u-bins

__device__ float   g_partials[BLOCKS];
__device__ unsigned int g_count = 0;
__device__ float   g_srgb_tab[SRGB_N];
__device__ float   g_labf_tab[LABF_N];
__device__ __half2 g_ht_tab[HT_N];

__global__ void init_tables_kernel() {
    int i = blockIdx.x * blockDim.x + threadIdx.x;
    if (i < SRGB_N) {
        float c = (i + 0.5f) / (float)SRGB_N;
        float hi = powf((c + 0.055f) / 1.055f, 2.4f);
        float lo = c / 12.92f;
        g_srgb_tab[i] = (c > 0.04045f) ? hi : lo;
    }
    if (i < LABF_N) {
        unsigned bits = LABF_BASE + ((unsigned)i << 16) + (1u << 15);
        float t = __uint_as_float(bits);
        g_labf_tab[i] = (t > 0.008856f) ? cbrtf(t) : fmaf(7.787f, t, 16.0f / 116.0f);
    }
    if (i < HT_N) {
        const float PI = 3.14159265358979323846f;
        int ubin = i & 1023, xng = (i >> 10) & 1, yng = (i >> 11) & 1;
        float u = (ubin + 0.5f) / 1024.0f;      // |sy| / (|sx|+|sy|)
        float phi = atan2f(u, 1.0f - u);        // [0, pi/2]
        if (xng) phi = PI - phi;
        if (yng) phi = -phi;
        if (phi < 0.0f) phi += 2.0f * PI;       // havg in [0, 2pi)
        float T = 1.0f - 0.17f * cosf(phi - PI / 6.0f) + 0.24f * cosf(2.0f * phi)
                + 0.32f * cosf(3.0f * phi + PI / 30.0f)
                - 0.20f * cosf(4.0f * phi - 7.0f * PI / 20.0f);
        float hdeg = phi * (180.0f / PI);
        float w = (hdeg - 275.0f) * (1.0f / 25.0f);
        g_ht_tab[i] = __floats2half2_rn(T, sinf(60.0f * expf(-w * w)));
    }
}

// ---------------- scalar helpers ----------------
__device__ __forceinline__ float warp_reduce(float v) {
#pragma unroll
    for (int o = 16; o > 0; o >>= 1) v += __shfl_down_sync(0xffffffffu, v, o);
    return v;
}
__device__ __forceinline__ float fsqrt_a(float x) {
    float r; asm("sqrt.approx.f32 %0, %1;" : "=f"(r) : "f"(x)); return r;
}
__device__ __forceinline__ float frcp_a(float x) {
    float r; asm("rcp.approx.f32 %0, %1;" : "=f"(r) : "f"(x)); return r;
}

// ---------------- f32x2 packed helpers ----------------
typedef unsigned long long u64;
__device__ __forceinline__ u64 pk2(float lo, float hi) {
    u64 r; asm("mov.b64 %0, {%1, %2};" : "=l"(r) : "f"(lo), "f"(hi)); return r;
}
__device__ __forceinline__ void up2(u64 v, float& lo, float& hi) {
    asm("mov.b64 {%0, %1}, %2;" : "=f"(lo), "=f"(hi) : "l"(v));
}
__device__ __forceinline__ u64 f2mul(u64 a, u64 b) {
    u64 r; asm("mul.rn.f32x2 %0, %1, %2;" : "=l"(r) : "l"(a), "l"(b)); return r;
}
__device__ __forceinline__ u64 f2add(u64 a, u64 b) {
    u64 r; asm("add.rn.f32x2 %0, %1, %2;" : "=l"(r) : "l"(a), "l"(b)); return r;
}
__device__ __forceinline__ u64 f2fma(u64 a, u64 b, u64 c) {
    u64 r; asm("fma.rn.f32x2 %0, %1, %2, %3;" : "=l"(r) : "l"(a), "l"(b), "l"(c)); return r;
}
__device__ __forceinline__ u64 f2neg(u64 a) { return a ^ 0x8000000080000000ull; }

// ---------------- table lookups (bit-trick indices) ----------------
__device__ __forceinline__ float srgb_lookup(const float* __restrict__ tab, float c) {
    unsigned bits = __float_as_uint(c + 1.0f);
    return tab[(bits >> 12) & 2047u];
}
__device__ __forceinline__ float labf_lookup(const float* __restrict__ tab, float t) {
    int idx = (int)(__float_as_uint(t) - LABF_BASE) >> 16;
    idx = max(idx, 0);
    return tab[idx];
}
__device__ __forceinline__ void rgb2lab(const float* __restrict__ stab,
                                        const float* __restrict__ ftab,
                                        float r, float g, float b,
                                        float& L, float& A, float& Bo) {
    float lr = srgb_lookup(stab, r);
    float lg = srgb_lookup(stab, g);
    float lb = srgb_lookup(stab, b);
    float xn = (0.4124564f / 0.95047f) * lr + (0.3575761f / 0.95047f) * lg + (0.1804375f / 0.95047f) * lb;
    float yn = 0.2126729f * lr + 0.7151522f * lg + 0.072175f * lb;
    float zn = (0.0193339f / 1.08883f) * lr + (0.119192f / 1.08883f) * lg + (0.9503041f / 1.08883f) * lb;
    float fx = labf_lookup(ftab, xn);
    float fy = labf_lookup(ftab, yn);
    float fz = labf_lookup(ftab, zn);
    L  = 116.0f * fy - 16.0f;
    A  = 500.0f * (fx - fy);
    Bo = 200.0f * (fy - fz);
}
__device__ __forceinline__ void hue_lookup(const __half2* __restrict__ httab,
                                           float sx, float sy, float& T, float& rtf) {
    float ax = fabsf(sx), ay = fabsf(sy);
    float u = ay * frcp_a(ax + ay);            // [0,1]; degenerate -> harmless bin
    unsigned b  = __float_as_uint(u + 1.0f);
    unsigned ux = __float_as_uint(sx);
    unsigned uy = __float_as_uint(sy);
    unsigned idx = ((b >> 13) & 1023u) | ((ux >> 21) & 1024u) | ((uy >> 20) & 2048u);
    float2 ht = __half22float2(httab[idx]);
    T = ht.x; rtf = ht.y;
}

// ratio = sqrt(S^7/(S^7+128*25^7)) = s7 * rsqrt(s7*(s7+P)+eps)   (1 MUFU)
__device__ __forceinline__ void ratio2(u64 pS, float& ru, float& rv) {
    u64 s2 = f2mul(pS, pS);
    u64 s4 = f2mul(s2, s2);
    u64 s7 = f2mul(f2mul(s4, s2), pS);
    float au, av; up2(s7, au, av);
    const float P = 6103515625.0f * 128.0f;
    ru = au * rsqrtf(fmaf(au, au + P, 1e-25f));
    rv = av * rsqrtf(fmaf(av, av + P, 1e-25f));
}

// ---------------- packed pair deltaE (rows u, v) ----------------
__device__ __forceinline__ void pair_de(const __half2* __restrict__ httab,
    u64 pONE, u64 p00225, u64 p00075, u64 p80, u64 pN100,
    float L1u, float a1u, float b1u, float L2u, float a2u, float b2u,
    float L1v, float a1v, float b1v, float L2v, float a2v, float b2v,
    float& deu, float& dev)
{
    u64 pA1 = pk2(a1u, a1v), pB1 = pk2(b1u, b1v);
    u64 pA2 = pk2(a2u, a2v), pB2 = pk2(b2u, b2v);
    u64 pB1sq = f2mul(pB1, pB1), pB2sq = f2mul(pB2, pB2);
    u64 pC1sq = f2fma(pA1, pA1, pB1sq), pC2sq = f2fma(pA2, pA2, pB2sq);
    float w0, w1, w2, w3;
    up2(pC1sq, w0, w1); up2(pC2sq, w2, w3);
    u64 pC1 = pk2(fsqrt_a(w0), fsqrt_a(w1));
    u64 pC2 = pk2(fsqrt_a(w2), fsqrt_a(w3));

    float ru, rv;
    ratio2(f2add(pC1, pC2), ru, rv);
    u64 pG = pk2(fmaf(-0.5f, ru, 1.5f), fmaf(-0.5f, rv, 1.5f));   // 1+G
    u64 pA1p = f2mul(pA1, pG), pA2p = f2mul(pA2, pG);
    u64 pC1psq = f2fma(pA1p, pA1p, pB1sq), pC2psq = f2fma(pA2p, pA2p, pB2sq);
    up2(pC1psq, w0, w1); up2(pC2psq, w2, w3);
    u64 pC1p = pk2(fsqrt_a(w0), fsqrt_a(w1));
    u64 pC2p = pk2(fsqrt_a(w2), fsqrt_a(w3));

    // dH = sign(cross) * sqrt(2*(C1p*C2p - dot))
    u64 pdot = f2fma(pA1p, pA2p, f2mul(pB1, pB2));
    u64 pcr  = f2fma(pB2, pA1p, f2neg(f2mul(pB1, pA2p)));
    u64 parg = f2add(f2mul(pC1p, pC2p), f2neg(pdot));
    parg = f2add(parg, parg);
    float agu, agv, cru, crv;
    up2(parg, agu, agv); up2(pcr, cru, crv);
    float dHu = copysignf(fsqrt_a(fmaxf(agu, 0.0f)), cru);
    float dHv = copysignf(fsqrt_a(fmaxf(agv, 0.0f)), crv);

    // hue bisector (sx, sy) per row
    u64 psx = f2fma(pA1p, pC2p, f2mul(pA2p, pC1p));
    u64 psy = f2fma(pB1,  pC2p, f2mul(pB2,  pC1p));
    float sxu, sxv, syu, syv;
    up2(psx, sxu, sxv); up2(psy, syu, syv);
    float Tu, rtfu, Tv, rtfv;
    hue_lookup(httab, sxu, syu, Tu, rtfu);
    hue_lookup(httab, sxv, syv, Tv, rtfv);

    // S' = C1p + C2p; RC via folded ratio; RT = -2*rtf*rc
    u64 pSp = f2add(pC1p, pC2p);
    float rcu, rcv;
    ratio2(pSp, rcu, rcv);
    u64 pRT = pk2(-2.0f * rtfu * rcu, -2.0f * rtfv * rcv);

    // SL = 1 + 0.0075*Lm'^2*rsqrt(80+Lm'^2), Lm' = L1+L2-100
    u64 pL1 = pk2(L1u, L1v), pL2 = pk2(L2u, L2v);
    u64 pLm = f2add(f2add(pL1, pL2), pN100);
    u64 pLm2 = f2mul(pLm, pLm);
    float ldu, ldv;
    up2(f2add(pLm2, p80), ldu, ldv);
    u64 pRS = pk2(rsqrtf(ldu), rsqrtf(ldv));
    u64 pSL = f2fma(f2mul(pLm2, p00075), pRS, pONE);
    u64 pSC = f2fma(p00225, pSp, pONE);
    u64 pSH = f2fma(f2mul(pSp, pk2(Tu, Tv)), p00075, pONE);

    // merged divides: one rcp per row
    u64 pSCSH = f2mul(pSC, pSH), pSLSH = f2mul(pSL, pSH), pSLSC = f2mul(pSL, pSC);
    float dnu, dnv;
    up2(f2mul(pSLSC, pSH), dnu, dnv);
    u64 pD = pk2(frcp_a(dnu), frcp_a(dnv));
    u64 xx = f2mul(f2add(pL2, f2neg(pL1)),   f2mul(pSCSH, pD));
    u64 yy = f2mul(f2add(pC2p, f2neg(pC1p)), f2mul(pSLSH, pD));
    u64 zz = f2mul(pk2(dHu, dHv),            f2mul(pSLSC, pD));
    u64 sum = f2fma(xx, xx, f2fma(yy, yy, f2fma(zz, zz, f2mul(pRT, f2mul(yy, zz)))));
    float su, sv;
    up2(sum, su, sv);
    deu = fsqrt_a(su);
    dev = fsqrt_a(sv);
}

__device__ __forceinline__ float pair_loss(const float* __restrict__ stab,
    const float* __restrict__ ftab, const __half2* __restrict__ httab,
    u64 pONE, u64 p00225, u64 p00075, u64 p80, u64 pN100,
    float pru, float pgu, float pbu, float tru, float tgu, float tbu,
    float prv, float pgv, float pbv, float trv, float tgv, float tbv)
{
    float d0 = pru - tru, d1 = pgu - tgu, d2 = pbu - tbu;
    float m_u = fmaf(d0, d0, fmaf(d1, d1, d2 * d2));
    d0 = prv - trv; d1 = pgv - tgv; d2 = pbv - tbv;
    float m_v = fmaf(d0, d0, fmaf(d1, d1, d2 * d2));

    float L1u, A1u, B1u, L2u, A2u, B2u, L1v, A1v, B1v, L2v, A2v, B2v;
    rgb2lab(stab, ftab, pru, pgu, pbu, L1u, A1u, B1u);
    rgb2lab(stab, ftab, tru, tgu, tbu, L2u, A2u, B2u);
    rgb2lab(stab, ftab, prv, pgv, pbv, L1v, A1v, B1v);
    rgb2lab(stab, ftab, trv, tgv, tbv, L2v, A2v, B2v);

    float deu, dev;
    pair_de(httab, pONE, p00225, p00075, p80, pN100,
            L1u, A1u, B1u, L2u, A2u, B2u,
            L1v, A1v, B1v, L2v, A2v, B2v, deu, dev);
    return fmaf(m_u + m_v, 0.2f / 3.0f, 0.8f * (deu + dev));
}

__global__ void __launch_bounds__(THREADS, 5)
de_loss_kernel(const float* __restrict__ pred, const float* __restrict__ targ,
               float* __restrict__ out, int n, float inv_n) {
    __shared__ float   s_srgb[SRGB_N];
    __shared__ float   s_labf[LABF_N];
    __shared__ __half2 s_ht[HT_N];
    {
        const float4* gs = reinterpret_cast<const float4*>(g_srgb_tab);
        float4* ss = reinterpret_cast<float4*>(s_srgb);
        for (int i = threadIdx.x; i < SRGB_N / 4; i += THREADS) ss[i] = gs[i];
        const float4* gf = reinterpret_cast<const float4*>(g_labf_tab);
        float4* sf = reinterpret_cast<float4*>(s_labf);
        for (int i = threadIdx.x; i < LABF_N / 4; i += THREADS) sf[i] = gf[i];
        const float4* gh = reinterpret_cast<const float4*>(g_ht_tab);
        float4* shh = reinterpret_cast<float4*>(s_ht);
        for (int i = threadIdx.x; i < HT_N / 4; i += THREADS) shh[i] = gh[i];
    }
    __syncthreads();

    const u64 pONE   = pk2(1.0f, 1.0f);
    const u64 p00225 = pk2(0.0225f, 0.0225f);
    const u64 p00075 = pk2(0.0075f, 0.0075f);
    const u64 p80    = pk2(80.0f, 80.0f);
    const u64 pN100  = pk2(-100.0f, -100.0f);

    const int P = gridDim.x * blockDim.x;
    const int tid = blockIdx.x * blockDim.x + threadIdx.x;
    float acc0 = 0.0f, acc1 = 0.0f;

    for (int base = tid * 4; base + 3 < n; base += P * 4) {
        const float4* p4 = reinterpret_cast<const float4*>(pred + (size_t)base * 3);
        const float4* t4 = reinterpret_cast<const float4*>(targ + (size_t)base * 3);
        float4 p0 = p4[0], p1 = p4[1], p2 = p4[2];
        float4 q0 = t4[0], q1 = t4[1], q2 = t4[2];

        acc0 += pair_loss(s_srgb, s_labf, s_ht, pONE, p00225, p00075, p80, pN100,
                          p0.x, p0.y, p0.z,  q0.x, q0.y, q0.z,
                          p0.w, p1.x, p1.y,  q0.w, q1.x, q1.y);
        acc1 += pair_loss(s_srgb, s_labf, s_ht, pONE, p00225, p00075, p80, pN100,
                          p1.z, p1.w, p2.x,  q1.z, q1.w, q2.x,
                          p2.y, p2.z, p2.w,  q2.y, q2.z, q2.w);
    }
    float acc = acc0 + acc1;
    int tail_start = (n / (P * 4)) * (P * 4);
    for (int i = tail_start + tid; i < n; i += P) {
        const float* p = pred + (size_t)i * 3;
        const float* t = targ + (size_t)i * 3;
        float l2 = pair_loss(s_srgb, s_labf, s_ht, pONE, p00225, p00075, p80, pN100,
                             p[0], p[1], p[2], t[0], t[1], t[2],
                             p[0], p[1], p[2], t[0], t[1], t[2]);
        acc += 0.5f * l2;
    }

    float v = warp_reduce(acc);
    __shared__ float sh[THREADS / 32];
    int lane = threadIdx.x & 31;
    int wid = threadIdx.x >> 5;
    if (lane == 0) sh[wid] = v;
    __syncthreads();
    if (wid == 0) {
        v = (lane < THREADS / 32) ? sh[lane] : 0.0f;
        v = warp_reduce(v);
        if (lane == 0) g_partials[blockIdx.x] = v;
    }

    __shared__ bool is_last;
    __threadfence();
    if (threadIdx.x == 0) {
        unsigned int c = atomicAdd(&g_count, 1u);
        is_last = (c == gridDim.x - 1);
    }
    __syncthreads();
    if (is_last) {
        float a = 0.0f;
        for (int i = threadIdx.x; i < BLOCKS; i += THREADS) a += g_partials[i];
        float w = warp_reduce(a);
        if (lane == 0) sh[wid] = w;
        __syncthreads();
        if (wid == 0) {
            w = (lane < THREADS / 32) ? sh[lane] : 0.0f;
            w = warp_reduce(w);
            if (lane == 0) {
                out[0] = w * inv_n;
                g_count = 0;
            }
        }
    }
}

extern "C" void kernel_launch(void* const* d_in, const int* in_sizes, int n_in,
                              void* d_out, int out_size) {
    const float* pred = (const float*)d_in[0];
    const float* targ = (const float*)d_in[1];
    int n = in_sizes[0] / 3;
    init_tables_kernel<<<(HT_N + 255) / 256, 256>>>();
    de_loss_kernel<<<BLOCKS, THREADS>>>(pred, targ, (float*)d_out, n, 1.0f / (float)n);
}